// round 4
// baseline (speedup 1.0000x reference)
#include <cuda_runtime.h>

#define Bb 8
#define Nn 4096
#define NC 13
#define BN (Bb*Nn)        // 32768 points per set
#define QTOT (2*BN)       // 65536 query mins (both directions)
#define TPB 128
#define QPT 4
#define QPB (TPB*QPT)     // 512 queries per block
#define SL 8              // candidate slices
#define SC (Nn/SL)        // 512 candidates per slice
#define SP (SC/2)         // 256 candidate pairs per slice

typedef unsigned long long u64;

__device__ float4       g_qa[BN];     // point_rec queries: (-2x,-2y,-2z,|p|^2)
__device__ float4       g_qb[BN];     // point queries
__device__ ulonglong2   g_cpa[BN];    // rec candidates pair-packed: pair p -> [2p]={xx',yy'} [2p+1]={zz',nn'}
__device__ ulonglong2   g_cpb[BN];    // point candidates pair-packed
__device__ int          g_min[QTOT];  // running min of squared dist (positive -> int order == float order)
__device__ float        g_fpart[64];
__device__ unsigned int g_ticket;     // zero-init; reset by finish_kernel each call

// ---- f32x2 helpers ----------------------------------------------------------
__device__ __forceinline__ u64 pk(float lo, float hi) {
    u64 r; asm("mov.b64 %0, {%1, %2};" : "=l"(r) : "f"(lo), "f"(hi)); return r;
}
__device__ __forceinline__ u64 fma2(u64 a, u64 b, u64 c) {
    u64 d; asm("fma.rn.f32x2 %0, %1, %2, %3;" : "=l"(d) : "l"(a), "l"(b), "l"(c)); return d;
}
__device__ __forceinline__ float min2(u64 v, float m) {
    float lo, hi;
    asm("mov.b64 {%0, %1}, %2;" : "=f"(lo), "=f"(hi) : "l"(v));
    return fminf(m, fminf(lo, hi));
}

// ---- pack + g_min init (pre-chamfer critical path only) ----------------------
__global__ void prep_kernel(const float* __restrict__ rec,
                            const float* __restrict__ pt) {
    int i = blockIdx.x * 256 + threadIdx.x;
    float x0 = rec[i*3+0], y0 = rec[i*3+1], z0 = rec[i*3+2];
    float na = fmaf(x0, x0, fmaf(y0, y0, z0*z0));
    g_qa[i] = make_float4(-2.f*x0, -2.f*y0, -2.f*z0, na);
    float x1 = pt[i*3+0], y1 = pt[i*3+1], z1 = pt[i*3+2];
    float nb = fmaf(x1, x1, fmaf(y1, y1, z1*z1));
    g_qb[i] = make_float4(-2.f*x1, -2.f*y1, -2.f*z1, nb);
    g_min[i]      = 0x7F800000;   // +inf
    g_min[BN + i] = 0x7F800000;
    if ((i & 1) == 0) {           // pack candidate pair (i, i+1)
        float xa = rec[i*3+3], ya = rec[i*3+4], za = rec[i*3+5];
        float naa = fmaf(xa, xa, fmaf(ya, ya, za*za));
        g_cpa[i]   = make_ulonglong2(pk(x0, xa), pk(y0, ya));
        g_cpa[i+1] = make_ulonglong2(pk(z0, za), pk(na, naa));
        float xb = pt[i*3+3], yb = pt[i*3+4], zb = pt[i*3+5];
        float nbb = fmaf(xb, xb, fmaf(yb, yb, zb*zb));
        g_cpb[i]   = make_ulonglong2(pk(x1, xb), pk(y1, yb));
        g_cpb[i+1] = make_ulonglong2(pk(z1, zb), pk(nb, nbb));
    }
}

// ---- chamfer: f32x2 over candidate pairs, atomic-min merge -------------------
// grid: (64, 8, 2): x = qblk*8 + slice, y = batch, z = direction
__global__ void __launch_bounds__(TPB, 8) chamfer_kernel() {
    __shared__ ulonglong2 scd[SC];   // 8KB: SP pairs x 2 entries

    const int qblk = blockIdx.x >> 3;
    const int sl   = blockIdx.x & 7;
    const int b    = blockIdx.y;
    const int dir  = blockIdx.z;
    const int t    = threadIdx.x;

    const float4*     __restrict__ Q  = dir ? g_qb : g_qa;
    const ulonglong2* __restrict__ Cp = dir ? g_cpa : g_cpb;

    const int qbase = b * Nn + qblk * QPB;
    float4 q0 = Q[qbase + t],         q1 = Q[qbase + TPB + t];
    float4 q2 = Q[qbase + 2*TPB + t], q3 = Q[qbase + 3*TPB + t];
    // duplicate each query component into both f32x2 lanes (once, outside loop)
    u64 x0 = pk(q0.x,q0.x), y0v = pk(q0.y,q0.y), z0v = pk(q0.z,q0.z);
    u64 x1 = pk(q1.x,q1.x), y1v = pk(q1.y,q1.y), z1v = pk(q1.z,q1.z);
    u64 x2 = pk(q2.x,q2.x), y2v = pk(q2.y,q2.y), z2v = pk(q2.z,q2.z);
    u64 x3 = pk(q3.x,q3.x), y3v = pk(q3.y,q3.y), z3v = pk(q3.z,q3.z);

    const ulonglong2* __restrict__ src = Cp + b * Nn + sl * SC;
    #pragma unroll
    for (int i = 0; i < SC / TPB; i++)
        scd[t + i * TPB] = src[t + i * TPB];
    __syncthreads();

    float m0 = 3.4e38f, m1 = 3.4e38f, m2 = 3.4e38f, m3 = 3.4e38f;
    #pragma unroll 16
    for (int jp = 0; jp < SP; jp++) {
        ulonglong2 p0 = scd[2*jp];      // {cx,cx'},{cy,cy'}
        ulonglong2 p1 = scd[2*jp + 1];  // {cz,cz'},{cn,cn'}
        u64 t0 = fma2(z0v, p1.x, p1.y); t0 = fma2(y0v, p0.y, t0); t0 = fma2(x0, p0.x, t0);
        u64 t1 = fma2(z1v, p1.x, p1.y); t1 = fma2(y1v, p0.y, t1); t1 = fma2(x1, p0.x, t1);
        u64 t2 = fma2(z2v, p1.x, p1.y); t2 = fma2(y2v, p0.y, t2); t2 = fma2(x2, p0.x, t2);
        u64 t3 = fma2(z3v, p1.x, p1.y); t3 = fma2(y3v, p0.y, t3); t3 = fma2(x3, p0.x, t3);
        m0 = min2(t0, m0);
        m1 = min2(t1, m1);
        m2 = min2(t2, m2);
        m3 = min2(t3, m3);
    }

    // add query norm -> true squared distance (>=0), merge across slices
    int* __restrict__ gm = g_min + (dir * Bb + b) * Nn + qblk * QPB;
    atomicMin(gm + t,         __float_as_int(m0 + q0.w));
    atomicMin(gm + t + TPB,   __float_as_int(m1 + q1.w));
    atomicMin(gm + t + 2*TPB, __float_as_int(m2 + q2.w));
    atomicMin(gm + t + 3*TPB, __float_as_int(m3 + q3.w));
}

// ---- finish: chamfer-sum + NLL gather + final combine in one kernel ----------
// 64 blocks x 256 threads. Last-arriving block (threadfence/ticket, the classic
// deterministic pattern) does the fixed-order final tree over 64 partials.
__global__ void finish_kernel(const float* __restrict__ prob,
                              const void* __restrict__ lab,
                              float* __restrict__ out) {
    __shared__ float sm[256];
    __shared__ int   s_is64;
    __shared__ int   s_last;
    const int t = threadIdx.x, bid = blockIdx.x;

    // chamfer part: 1024 mins per block
    int4 v = ((const int4*)g_min)[bid * 256 + t];
    float c = (__int_as_float(v.x) + __int_as_float(v.y)) +
              (__int_as_float(v.z) + __int_as_float(v.w));

    // label width probe: labels < 13; if int64 every odd 32-bit word is 0.
    const int* l32 = (const int*)lab;
    if (t == 0) { s_is64 = 1; s_last = 0; }
    __syncthreads();
    if (l32[2*t + 1] != 0) s_is64 = 0;   // words [1,512): in-bounds either width
    __syncthreads();

    // seg part: 512 points per block
    int i0 = bid * 512 + t, i1 = i0 + 256;
    int lb0, lb1;
    if (s_is64) {
        lb0 = (int)((const long long*)lab)[i0];
        lb1 = (int)((const long long*)lab)[i1];
    } else {
        lb0 = l32[i0];
        lb1 = l32[i1];
    }
    float sg = prob[i0 * NC + lb0] + prob[i1 * NC + lb1];

    sm[t] = c - sg;
    __syncthreads();
    #pragma unroll
    for (int s = 128; s > 0; s >>= 1) {
        if (t < s) sm[t] += sm[t + s];
        __syncthreads();
    }

    if (t == 0) {
        g_fpart[bid] = sm[0];
        __threadfence();
        unsigned tk = atomicAdd(&g_ticket, 1u);
        if (tk == 63u) s_last = 1;
    }
    __syncthreads();

    if (s_last) {
        __threadfence();
        if (t < 64) sm[t] = g_fpart[t];
        __syncthreads();
        #pragma unroll
        for (int s = 32; s > 0; s >>= 1) {
            if (t < s) sm[t] += sm[t + s];
            __syncthreads();
        }
        if (t == 0) {
            out[0] = sm[0] * (1.0f / (float)BN);
            g_ticket = 0u;   // reset for next graph replay
        }
    }
}

extern "C" void kernel_launch(void* const* d_in, const int* in_sizes, int n_in,
                              void* d_out, int out_size) {
    const float* seg_prob  = (const float*)d_in[0];
    const void*  seg_label = (const void*)d_in[1];
    const float* point_rec = (const float*)d_in[2];
    const float* point     = (const float*)d_in[3];

    prep_kernel<<<128, 256>>>(point_rec, point);
    chamfer_kernel<<<dim3(64, 8, 2), TPB>>>();
    finish_kernel<<<64, 256>>>(seg_prob, seg_label, (float*)d_out);
}

// round 5
// speedup vs baseline: 1.0529x; 1.0529x over previous
#include <cuda_runtime.h>

#define Bb 8
#define Nn 4096
#define NC 13
#define BN (Bb*Nn)        // 32768 points per set
#define QTOT (2*BN)       // 65536 query mins (both directions)
#define TPB 128
#define QPT 4
#define QPB (TPB*QPT)     // 512 queries per block
#define SL 8              // candidate slices
#define SC (Nn/SL)        // 512 candidates per slice
#define SP (SC/2)         // 256 candidate pairs per slice
#define ENC 0x7F800000    // k = ENC - float_bits(d); zero-init == d=+inf; min d == max k

typedef unsigned long long u64;

__device__ int          g_min[QTOT];  // encoded mins; zero == +inf; reset to 0 by finish each call
__device__ float        g_fpart[64];
__device__ unsigned int g_ticket;     // zero-init; reset by finish each call

// ---- f32x2 helpers ----------------------------------------------------------
__device__ __forceinline__ u64 pk(float lo, float hi) {
    u64 r; asm("mov.b64 %0, {%1, %2};" : "=l"(r) : "f"(lo), "f"(hi)); return r;
}
__device__ __forceinline__ u64 fma2(u64 a, u64 b, u64 c) {
    u64 d; asm("fma.rn.f32x2 %0, %1, %2, %3;" : "=l"(d) : "l"(a), "l"(b), "l"(c)); return d;
}
__device__ __forceinline__ float min2(u64 v, float m) {
    float lo, hi;
    asm("mov.b64 {%0, %1}, %2;" : "=f"(lo), "=f"(hi) : "l"(v));
    return fminf(m, fminf(lo, hi));
}

// ---- chamfer: self-packing, f32x2 over candidate pairs, encoded atomic-max ---
// grid: (64, 8, 2): x = qblk*8 + slice, y = batch, z = direction
__global__ void __launch_bounds__(TPB, 7) chamfer_kernel(const float* __restrict__ rec,
                                                         const float* __restrict__ pt) {
    __shared__ ulonglong2 scd[SC];   // 8KB: SP pairs x 2 entries

    const int qblk = blockIdx.x >> 3;
    const int sl   = blockIdx.x & 7;
    const int b    = blockIdx.y;
    const int dir  = blockIdx.z;
    const int t    = threadIdx.x;

    const float* __restrict__ Qraw = dir ? pt  : rec;
    const float* __restrict__ Craw = dir ? rec : pt;

    // pack 4 queries from raw input: dup(-2x), dup(-2y), dup(-2z), norm
    const int qbase = b * Nn + qblk * QPB;
    u64 qx[QPT], qy[QPT], qz[QPT];
    float qn[QPT];
    #pragma unroll
    for (int k = 0; k < QPT; k++) {
        const float* p = Qraw + (size_t)(qbase + t + k * TPB) * 3;
        float x = p[0], y = p[1], z = p[2];
        qn[k] = fmaf(x, x, fmaf(y, y, z * z));
        qx[k] = pk(-2.f * x, -2.f * x);
        qy[k] = pk(-2.f * y, -2.f * y);
        qz[k] = pk(-2.f * z, -2.f * z);
    }

    // stage + pack this slice's candidates: pair p -> [2p]={xx',yy'} [2p+1]={zz',nn'}
    const int cbase = b * Nn + sl * SC;
    #pragma unroll
    for (int i = 0; i < SP / TPB; i++) {
        int p = t + i * TPB;
        const float* c = Craw + (size_t)(cbase + 2 * p) * 3;
        float x0 = c[0], y0 = c[1], z0 = c[2];
        float x1 = c[3], y1 = c[4], z1 = c[5];
        float n0 = fmaf(x0, x0, fmaf(y0, y0, z0 * z0));
        float n1 = fmaf(x1, x1, fmaf(y1, y1, z1 * z1));
        scd[2 * p]     = make_ulonglong2(pk(x0, x1), pk(y0, y1));
        scd[2 * p + 1] = make_ulonglong2(pk(z0, z1), pk(n0, n1));
    }
    __syncthreads();

    float m0 = 3.4e38f, m1 = 3.4e38f, m2 = 3.4e38f, m3 = 3.4e38f;
    #pragma unroll 16
    for (int jp = 0; jp < SP; jp++) {
        ulonglong2 p0 = scd[2 * jp];      // {cx,cx'},{cy,cy'}
        ulonglong2 p1 = scd[2 * jp + 1];  // {cz,cz'},{cn,cn'}
        u64 t0 = fma2(qz[0], p1.x, p1.y); t0 = fma2(qy[0], p0.y, t0); t0 = fma2(qx[0], p0.x, t0);
        u64 t1 = fma2(qz[1], p1.x, p1.y); t1 = fma2(qy[1], p0.y, t1); t1 = fma2(qx[1], p0.x, t1);
        u64 t2 = fma2(qz[2], p1.x, p1.y); t2 = fma2(qy[2], p0.y, t2); t2 = fma2(qx[2], p0.x, t2);
        u64 t3 = fma2(qz[3], p1.x, p1.y); t3 = fma2(qy[3], p0.y, t3); t3 = fma2(qx[3], p0.x, t3);
        m0 = min2(t0, m0);
        m1 = min2(t1, m1);
        m2 = min2(t2, m2);
        m3 = min2(t3, m3);
    }

    // d = partial + qnorm; encoded merge: k = ENC - bits(d), atomicMax, 0-init == +inf
    int* __restrict__ gm = g_min + (dir * Bb + b) * Nn + qblk * QPB;
    atomicMax(gm + t,           ENC - __float_as_int(m0 + qn[0]));
    atomicMax(gm + t + TPB,     ENC - __float_as_int(m1 + qn[1]));
    atomicMax(gm + t + 2 * TPB, ENC - __float_as_int(m2 + qn[2]));
    atomicMax(gm + t + 3 * TPB, ENC - __float_as_int(m3 + qn[3]));
}

// ---- finish: chamfer-sum + NLL gather + final combine + state reset ----------
// 64 blocks x 256 threads; last-arriving block does the fixed-order final tree.
__global__ void finish_kernel(const float* __restrict__ prob,
                              const void* __restrict__ lab,
                              float* __restrict__ out) {
    __shared__ float sm[256];
    __shared__ int   s_is64;
    __shared__ int   s_last;
    const int t = threadIdx.x, bid = blockIdx.x;

    // chamfer part: decode 4 mins per thread, then reset storage to 0 for next replay
    int4* gm4 = (int4*)g_min + bid * 256 + t;
    int4 v = *gm4;
    float c = (__int_as_float(ENC - v.x) + __int_as_float(ENC - v.y)) +
              (__int_as_float(ENC - v.z) + __int_as_float(ENC - v.w));
    *gm4 = make_int4(0, 0, 0, 0);

    // label width probe: labels < 13; if int64 every odd 32-bit word is 0.
    const int* l32 = (const int*)lab;
    if (t == 0) { s_is64 = 1; s_last = 0; }
    __syncthreads();
    if (l32[2 * t + 1] != 0) s_is64 = 0;   // words [1,512): in-bounds either width
    __syncthreads();

    // seg part: 512 points per block
    int i0 = bid * 512 + t, i1 = i0 + 256;
    int lb0, lb1;
    if (s_is64) {
        lb0 = (int)((const long long*)lab)[i0];
        lb1 = (int)((const long long*)lab)[i1];
    } else {
        lb0 = l32[i0];
        lb1 = l32[i1];
    }
    float sg = prob[i0 * NC + lb0] + prob[i1 * NC + lb1];

    sm[t] = c - sg;
    __syncthreads();
    #pragma unroll
    for (int s = 128; s > 0; s >>= 1) {
        if (t < s) sm[t] += sm[t + s];
        __syncthreads();
    }

    if (t == 0) {
        g_fpart[bid] = sm[0];
        __threadfence();
        unsigned tk = atomicAdd(&g_ticket, 1u);
        if (tk == 63u) s_last = 1;
    }
    __syncthreads();

    if (s_last) {
        __threadfence();
        if (t < 64) sm[t] = g_fpart[t];
        __syncthreads();
        #pragma unroll
        for (int s = 32; s > 0; s >>= 1) {
            if (t < s) sm[t] += sm[t + s];
            __syncthreads();
        }
        if (t == 0) {
            out[0] = sm[0] * (1.0f / (float)BN);
            g_ticket = 0u;   // reset for next graph replay
        }
    }
}

extern "C" void kernel_launch(void* const* d_in, const int* in_sizes, int n_in,
                              void* d_out, int out_size) {
    const float* seg_prob  = (const float*)d_in[0];
    const void*  seg_label = (const void*)d_in[1];
    const float* point_rec = (const float*)d_in[2];
    const float* point     = (const float*)d_in[3];

    chamfer_kernel<<<dim3(64, 8, 2), TPB>>>(point_rec, point);
    finish_kernel<<<64, 256>>>(seg_prob, seg_label, (float*)d_out);
}